// round 10
// baseline (speedup 1.0000x reference)
#include <cuda_runtime.h>
#include <cstdint>

#define COLS 8192
#define COLS4 2048
#define ROWS 1024
#define SCALE 0.75f
#define QTR 2048              // floats per quarter-row

// Scratch (no allocation allowed). 32B-aligned for LDG.256.
__device__ __align__(32) float g_wtotal[COLS];

// LDG.256 + evict_last (x stream: L2-resident across graph replays).
__device__ __forceinline__ void ldg256_el(const float* p, float4& a, float4& b) {
    unsigned r0, r1, r2, r3, r4, r5, r6, r7;
    asm volatile("ld.global.nc.L2::evict_last.v8.b32 {%0,%1,%2,%3,%4,%5,%6,%7}, [%8];"
        : "=r"(r0), "=r"(r1), "=r"(r2), "=r"(r3),
          "=r"(r4), "=r"(r5), "=r"(r6), "=r"(r7)
        : "l"(p));
    a.x = __uint_as_float(r0); a.y = __uint_as_float(r1);
    a.z = __uint_as_float(r2); a.w = __uint_as_float(r3);
    b.x = __uint_as_float(r4); b.y = __uint_as_float(r5);
    b.z = __uint_as_float(r6); b.w = __uint_as_float(r7);
}
// Plain LDG.256 (w: L1-hot, 8 KB per warp's quarter).
__device__ __forceinline__ void ldg256(const float* p, float4& a, float4& b) {
    unsigned r0, r1, r2, r3, r4, r5, r6, r7;
    asm volatile("ld.global.nc.v8.b32 {%0,%1,%2,%3,%4,%5,%6,%7}, [%8];"
        : "=r"(r0), "=r"(r1), "=r"(r2), "=r"(r3),
          "=r"(r4), "=r"(r5), "=r"(r6), "=r"(r7)
        : "l"(p));
    a.x = __uint_as_float(r0); a.y = __uint_as_float(r1);
    a.z = __uint_as_float(r2); a.w = __uint_as_float(r3);
    b.x = __uint_as_float(r4); b.y = __uint_as_float(r5);
    b.z = __uint_as_float(r6); b.w = __uint_as_float(r7);
}

// ---------------- Kernel 1: w_total[c] = sum_g wsums[g][c] ----------------
__global__ __launch_bounds__(256) void reduce_w_kernel(const float* __restrict__ wsums) {
    const int lcol  = threadIdx.x & 31;
    const int chunk = threadIdx.x >> 5;               // 0..7, 4 groups each
    const int c4    = blockIdx.x * 32 + lcol;

    const float4* __restrict__ w4 = reinterpret_cast<const float4*>(wsums);
    float4 s = make_float4(0.f, 0.f, 0.f, 0.f);
#pragma unroll
    for (int g = 0; g < 4; ++g) {
        float4 v = w4[(size_t)(chunk * 4 + g) * COLS4 + c4];
        s.x += v.x; s.y += v.y; s.z += v.z; s.w += v.w;
    }

    __shared__ float4 sm[8][32];
    sm[chunk][lcol] = s;
    __syncthreads();

    if (threadIdx.x < 32) {
        float4 r = make_float4(0.f, 0.f, 0.f, 0.f);
#pragma unroll
        for (int c = 0; c < 8; ++c) {
            float4 v = sm[c][threadIdx.x];
            r.x += v.x; r.y += v.y; r.z += v.z; r.w += v.w;
        }
        reinterpret_cast<float4*>(g_wtotal)[c4] = r;
    }
}

// ---------------- Kernel 2: warp-per-quarter-row long-loop matvec ----------------
// Grid 512 x 256 threads (8 warps). Warp wid owns quarter (wid&3) of row
// bid*2+(wid>>2): 8-iteration stride loop, unroll 4, no sync in the stream.
// 3 resident blocks/SM (reg cap 84) stagger their prologues/epilogues.
__global__ __launch_bounds__(256, 3) void dot_warp_kernel(const float* __restrict__ x,
                                                          float* __restrict__ out) {
    const int t   = threadIdx.x;
    const int wid = t >> 5;
    const int lid = t & 31;
    const int row = blockIdx.x * 2 + (wid >> 2);
    const int q   = wid & 3;

    const float* __restrict__ xr = x + (size_t)row * COLS + q * QTR + lid * 8;
    const float* __restrict__ wr = g_wtotal + q * QTR + lid * 8;

    float p0 = 0.f, p1 = 0.f, p2 = 0.f, p3 = 0.f;
#pragma unroll 4
    for (int i = 0; i < 8; ++i) {
        float4 a0, a1, b0, b1;
        ldg256_el(xr + i * 256, a0, a1);
        ldg256  (wr + i * 256, b0, b1);
        p0 = fmaf(a0.x, b0.x, p0); p1 = fmaf(a0.y, b0.y, p1);
        p2 = fmaf(a0.z, b0.z, p2); p3 = fmaf(a0.w, b0.w, p3);
        p0 = fmaf(a1.x, b1.x, p0); p1 = fmaf(a1.y, b1.y, p1);
        p2 = fmaf(a1.z, b1.z, p2); p3 = fmaf(a1.w, b1.w, p3);
    }
    float s = (p0 + p1) + (p2 + p3);

    // Warp reduce.
#pragma unroll
    for (int o = 16; o > 0; o >>= 1)
        s += __shfl_xor_sync(0xFFFFFFFFu, s, o);

    __shared__ float red[8];
    if (lid == 0) red[wid] = s;
    __syncthreads();

    if (t < 2)
        out[blockIdx.x * 2 + t] = SCALE * ((red[4 * t + 0] + red[4 * t + 1])
                                         + (red[4 * t + 2] + red[4 * t + 3]));
}

extern "C" void kernel_launch(void* const* d_in, const int* in_sizes, int n_in,
                              void* d_out, int out_size) {
    const float* x     = (const float*)d_in[0];  // [1024, 8192] f32
    const float* wsums = (const float*)d_in[1];  // [32, 8192] f32
    float* out         = (float*)d_out;          // [1024, 1] f32

    reduce_w_kernel<<<COLS4 / 32, 256>>>(wsums);
    dot_warp_kernel<<<ROWS / 2, 256>>>(x, out);
}

// round 11
// speedup vs baseline: 1.2657x; 1.2657x over previous
#include <cuda_runtime.h>
#include <cstdint>

#define COLS 8192
#define COLS4 2048
#define ROWS 1024
#define SCALE 0.75f
#define HALF 4096             // floats per half-row

// Scratch (no allocation allowed). 32B-aligned for LDG.256.
__device__ __align__(32) float g_wtotal[COLS];

// LDG.256 + evict_last (x stream: L2-resident across graph replays).
__device__ __forceinline__ void ldg256_el(const float* p, float4& a, float4& b) {
    unsigned r0, r1, r2, r3, r4, r5, r6, r7;
    asm volatile("ld.global.nc.L2::evict_last.v8.b32 {%0,%1,%2,%3,%4,%5,%6,%7}, [%8];"
        : "=r"(r0), "=r"(r1), "=r"(r2), "=r"(r3),
          "=r"(r4), "=r"(r5), "=r"(r6), "=r"(r7)
        : "l"(p));
    a.x = __uint_as_float(r0); a.y = __uint_as_float(r1);
    a.z = __uint_as_float(r2); a.w = __uint_as_float(r3);
    b.x = __uint_as_float(r4); b.y = __uint_as_float(r5);
    b.z = __uint_as_float(r6); b.w = __uint_as_float(r7);
}
// Plain LDG.256 (w: L1/L2-hot, 16 KB per warp's half).
__device__ __forceinline__ void ldg256(const float* p, float4& a, float4& b) {
    unsigned r0, r1, r2, r3, r4, r5, r6, r7;
    asm volatile("ld.global.nc.v8.b32 {%0,%1,%2,%3,%4,%5,%6,%7}, [%8];"
        : "=r"(r0), "=r"(r1), "=r"(r2), "=r"(r3),
          "=r"(r4), "=r"(r5), "=r"(r6), "=r"(r7)
        : "l"(p));
    a.x = __uint_as_float(r0); a.y = __uint_as_float(r1);
    a.z = __uint_as_float(r2); a.w = __uint_as_float(r3);
    b.x = __uint_as_float(r4); b.y = __uint_as_float(r5);
    b.z = __uint_as_float(r6); b.w = __uint_as_float(r7);
}

// ---------------- Kernel 1: w_total[c] = sum_g wsums[g][c] ----------------
__global__ __launch_bounds__(256) void reduce_w_kernel(const float* __restrict__ wsums) {
    const int lcol  = threadIdx.x & 31;
    const int chunk = threadIdx.x >> 5;               // 0..7, 4 groups each
    const int c4    = blockIdx.x * 32 + lcol;

    const float4* __restrict__ w4 = reinterpret_cast<const float4*>(wsums);
    float4 s = make_float4(0.f, 0.f, 0.f, 0.f);
#pragma unroll
    for (int g = 0; g < 4; ++g) {
        float4 v = w4[(size_t)(chunk * 4 + g) * COLS4 + c4];
        s.x += v.x; s.y += v.y; s.z += v.z; s.w += v.w;
    }

    __shared__ float4 sm[8][32];
    sm[chunk][lcol] = s;
    __syncthreads();

    if (threadIdx.x < 32) {
        float4 r = make_float4(0.f, 0.f, 0.f, 0.f);
#pragma unroll
        for (int c = 0; c < 8; ++c) {
            float4 v = sm[c][threadIdx.x];
            r.x += v.x; r.y += v.y; r.z += v.z; r.w += v.w;
        }
        reinterpret_cast<float4*>(g_wtotal)[c4] = r;
    }
}

// ---------------- Kernel 2: warp-per-half-row long-loop matvec ----------------
// Grid 256 x 256 threads (8 warps). Warp wid owns half (wid&1) of row
// bid*4+(wid>>1): 16-iteration stride loop (the R9 winner depth), unroll 4,
// no sync in the stream. 256 blocks cover all 148 SMs (1-2 resident each,
// staggered prologues/epilogues).
__global__ __launch_bounds__(256, 3) void dot_warp_kernel(const float* __restrict__ x,
                                                          float* __restrict__ out) {
    const int t   = threadIdx.x;
    const int wid = t >> 5;
    const int lid = t & 31;
    const int row  = blockIdx.x * 4 + (wid >> 1);
    const int half = wid & 1;

    const float* __restrict__ xr = x + (size_t)row * COLS + half * HALF + lid * 8;
    const float* __restrict__ wr = g_wtotal + half * HALF + lid * 8;

    float p0 = 0.f, p1 = 0.f, p2 = 0.f, p3 = 0.f;
#pragma unroll 4
    for (int i = 0; i < 16; ++i) {
        float4 a0, a1, b0, b1;
        ldg256_el(xr + i * 256, a0, a1);
        ldg256  (wr + i * 256, b0, b1);
        p0 = fmaf(a0.x, b0.x, p0); p1 = fmaf(a0.y, b0.y, p1);
        p2 = fmaf(a0.z, b0.z, p2); p3 = fmaf(a0.w, b0.w, p3);
        p0 = fmaf(a1.x, b1.x, p0); p1 = fmaf(a1.y, b1.y, p1);
        p2 = fmaf(a1.z, b1.z, p2); p3 = fmaf(a1.w, b1.w, p3);
    }
    float s = (p0 + p1) + (p2 + p3);

    // Warp reduce.
#pragma unroll
    for (int o = 16; o > 0; o >>= 1)
        s += __shfl_xor_sync(0xFFFFFFFFu, s, o);

    __shared__ float red[8];
    if (lid == 0) red[wid] = s;
    __syncthreads();

    if (t < 4)
        out[blockIdx.x * 4 + t] = SCALE * (red[2 * t] + red[2 * t + 1]);
}

extern "C" void kernel_launch(void* const* d_in, const int* in_sizes, int n_in,
                              void* d_out, int out_size) {
    const float* x     = (const float*)d_in[0];  // [1024, 8192] f32
    const float* wsums = (const float*)d_in[1];  // [32, 8192] f32
    float* out         = (float*)d_out;          // [1024, 1] f32

    reduce_w_kernel<<<COLS4 / 32, 256>>>(wsums);
    dot_warp_kernel<<<ROWS / 4, 256>>>(x, out);
}